// round 1
// baseline (speedup 1.0000x reference)
#include <cuda_runtime.h>

// ---------------- problem constants ----------------
#define TB    64           // samples per block
#define PADX  68           // x tile row pad (floats)
#define PADH  65           // h1 tile row pad
#define PADW  132          // W2 chunk row pad
#define SM_X  (64*PADX)    // 4352 floats
#define SM_H  (256*PADH)   // 16640 floats
#define SM_W  (32*PADW)    // 4224 floats
#define SM_E  1984         // emb tables 62*2*16
#define SMEM_FLOATS (SM_X + SM_H + SM_W + SM_E)
#define SMEM_BYTES  (SMEM_FLOATS * 4)   // 108800 B

// scratch (device globals — no allocation allowed)
__device__ float g_A1[256 * 64];    // W1 @ M   (256 x 64)
__device__ float g_c1[256];         // W1 @ base + b1
__device__ float g_W2T[256 * 128];  // W2 transposed

// ---------------- precompute: A1, c1 ----------------
__global__ void prep_A1(const float* __restrict__ emb, const float* __restrict__ Wc,
                        const float* __restrict__ bc,  const float* __restrict__ W1,
                        const float* __restrict__ b1) {
    int j = blockIdx.x;      // output neuron 0..255
    int f = threadIdx.x;     // feature 0..63
    const float* w = W1 + j * 1024;
    float af = 0.f, cpart = 0.f;
    if (f < 62) {
        #pragma unroll
        for (int d = 0; d < 16; d++) {
            float wv = w[f * 16 + d];
            float e0 = emb[f * 32 + d];
            float e1 = emb[f * 32 + 16 + d];
            af    += wv * (e1 - e0);
            cpart += wv * e0;
        }
    } else {
        int jc = f - 62;
        #pragma unroll
        for (int m = 0; m < 32; m++) {
            float wv = w[992 + m];
            af += wv * Wc[m * 2 + jc];
            if (jc == 0) cpart += wv * bc[m];
        }
    }
    g_A1[j * 64 + f] = af;
    __shared__ float red[64];
    red[f] = cpart;
    __syncthreads();
    if (f == 0) {
        float s = b1[j];
        #pragma unroll
        for (int t = 0; t < 64; t++) s += red[t];
        g_c1[j] = s;
    }
}

// ---------------- precompute: W2^T ----------------
__global__ void prep_W2T(const float* __restrict__ W2) {
    int idx = blockIdx.x * 256 + threadIdx.x;  // 0..32767
    int i = idx >> 7, k = idx & 127;
    g_W2T[idx] = W2[k * 256 + i];
}

// ---------------- fused main kernel ----------------
__global__ __launch_bounds__(256, 2) void deepfm_main(
    const float* __restrict__ x,   const float* __restrict__ emb,
    const float* __restrict__ Wc,  const float* __restrict__ bc,
    const float* __restrict__ Wf,  const float* __restrict__ bf,
    const float* __restrict__ b2,  float* __restrict__ out) {
    extern __shared__ float sm[];
    float* xsT = sm;                          // [64 f][PADX s]  (transposed x tile)
    float* h1T = sm + SM_X;                   // [256 j][PADH s] (ReLU(z1) transposed)
    float* ws  = sm + SM_X + SM_H;            // [32 ii][PADW k] W2^T chunk
    float* es  = sm + SM_X + SM_H + SM_W;     // emb tables

    const int tid = threadIdx.x;
    const int b0  = blockIdx.x * TB;
    const float* xblk = x + (size_t)b0 * 64;

    // ---- load x tile (coalesced read, transposed store) + emb tables ----
    #pragma unroll
    for (int r = 0; r < 16; r++) {
        int lin = r * 256 + tid;
        int s = lin >> 6, f = lin & 63;
        xsT[f * PADX + s] = xblk[lin];
    }
    for (int idx = tid; idx < SM_E; idx += 256) es[idx] = emb[idx];
    __syncthreads();

    // ---- FM phase: 4 threads per sample, thread u owns dims 4u..4u+3 ----
    {
        int s = tid >> 2, u = tid & 3;
        float se0 = 0.f, se1 = 0.f, se2 = 0.f, se3 = 0.f, ssq = 0.f, first = 0.f;
        for (int f = 0; f < 62; f++) {
            float xv = xsT[f * PADX + s];
            int off = f * 32 + (xv > 0.5f ? 16 : 0) + u * 4;
            float v0 = es[off], v1 = es[off + 1], v2 = es[off + 2], v3 = es[off + 3];
            se0 += v0; se1 += v1; se2 += v2; se3 += v3;
            ssq += v0 * v0 + v1 * v1 + v2 * v2 + v3 * v3;
        }
        float x62 = xsT[62 * PADX + s], x63 = xsT[63 * PADX + s];
        #pragma unroll
        for (int c = 0; c < 2; c++) {
            #pragma unroll
            for (int dd = 0; dd < 4; dd++) {
                int m = c * 16 + u * 4 + dd;
                float v = __ldg(&bc[m]) + x62 * __ldg(&Wc[m * 2]) + x63 * __ldg(&Wc[m * 2 + 1]);
                if (dd == 0) se0 += v; else if (dd == 1) se1 += v;
                else if (dd == 2) se2 += v; else se3 += v;
                ssq += v * v;
            }
        }
        #pragma unroll
        for (int ff = 0; ff < 16; ff++) {
            int f = u * 16 + ff;
            first += xsT[f * PADX + s] * __ldg(&Wf[f]);
        }
        float part = se0 * se0 + se1 * se1 + se2 * se2 + se3 * se3;
        part  += __shfl_xor_sync(0xffffffffu, part, 1);
        part  += __shfl_xor_sync(0xffffffffu, part, 2);
        ssq   += __shfl_xor_sync(0xffffffffu, ssq, 1);
        ssq   += __shfl_xor_sync(0xffffffffu, ssq, 2);
        first += __shfl_xor_sync(0xffffffffu, first, 1);
        first += __shfl_xor_sync(0xffffffffu, first, 2);
        if (u == 0)
            out[(size_t)(b0 + s) * 129] = first + __ldg(&bf[0]) + 0.5f * (part - ssq);
    }

    // ---- Phase B: z1 = c1 + A1 @ x  (thread tid = output neuron j) ----
    {
        int j = tid;
        float a[64];
        const float4* arow = (const float4*)(g_A1 + j * 64);
        #pragma unroll
        for (int q = 0; q < 16; q++) ((float4*)a)[q] = __ldg(&arow[q]);
        float cj = g_c1[j];
        #pragma unroll 1
        for (int s0 = 0; s0 < 64; s0 += 4) {
            float a0 = cj, a1v = cj, a2 = cj, a3 = cj;
            #pragma unroll
            for (int f = 0; f < 64; f++) {
                float4 xv = *(const float4*)&xsT[f * PADX + s0];   // broadcast
                a0  += a[f] * xv.x; a1v += a[f] * xv.y;
                a2  += a[f] * xv.z; a3  += a[f] * xv.w;
            }
            h1T[j * PADH + s0]     = fmaxf(a0, 0.f);
            h1T[j * PADH + s0 + 1] = fmaxf(a1v, 0.f);
            h1T[j * PADH + s0 + 2] = fmaxf(a2, 0.f);
            h1T[j * PADH + s0 + 3] = fmaxf(a3, 0.f);
        }
    }
    __syncthreads();

    // ---- Phase C: out[:,1:129] = ReLU(W2 @ h1 + b2), 4x8 register tile ----
    {
        int tx = tid & 15, ty = tid >> 4;
        int sc = ty * 4, k0 = tx * 8;
        float acc[4][8];
        #pragma unroll
        for (int u = 0; u < 8; u++) {
            float bv = __ldg(&b2[k0 + u]);
            acc[0][u] = bv; acc[1][u] = bv; acc[2][u] = bv; acc[3][u] = bv;
        }
        for (int i0 = 0; i0 < 256; i0 += 32) {
            #pragma unroll
            for (int r = 0; r < 16; r++) {
                int lin = r * 256 + tid;
                int ii = lin >> 7, k = lin & 127;
                ws[ii * PADW + k] = __ldg(&g_W2T[(i0 + ii) * 128 + k]);
            }
            __syncthreads();
            #pragma unroll
            for (int ii = 0; ii < 32; ii++) {
                float4 w0 = *(const float4*)&ws[ii * PADW + k0];
                float4 w1 = *(const float4*)&ws[ii * PADW + k0 + 4];
                float h0  = h1T[(i0 + ii) * PADH + sc];
                float h1v = h1T[(i0 + ii) * PADH + sc + 1];
                float h2  = h1T[(i0 + ii) * PADH + sc + 2];
                float h3  = h1T[(i0 + ii) * PADH + sc + 3];
                acc[0][0] += h0 * w0.x; acc[0][1] += h0 * w0.y; acc[0][2] += h0 * w0.z; acc[0][3] += h0 * w0.w;
                acc[0][4] += h0 * w1.x; acc[0][5] += h0 * w1.y; acc[0][6] += h0 * w1.z; acc[0][7] += h0 * w1.w;
                acc[1][0] += h1v * w0.x; acc[1][1] += h1v * w0.y; acc[1][2] += h1v * w0.z; acc[1][3] += h1v * w0.w;
                acc[1][4] += h1v * w1.x; acc[1][5] += h1v * w1.y; acc[1][6] += h1v * w1.z; acc[1][7] += h1v * w1.w;
                acc[2][0] += h2 * w0.x; acc[2][1] += h2 * w0.y; acc[2][2] += h2 * w0.z; acc[2][3] += h2 * w0.w;
                acc[2][4] += h2 * w1.x; acc[2][5] += h2 * w1.y; acc[2][6] += h2 * w1.z; acc[2][7] += h2 * w1.w;
                acc[3][0] += h3 * w0.x; acc[3][1] += h3 * w0.y; acc[3][2] += h3 * w0.z; acc[3][3] += h3 * w0.w;
                acc[3][4] += h3 * w1.x; acc[3][5] += h3 * w1.y; acc[3][6] += h3 * w1.z; acc[3][7] += h3 * w1.w;
            }
            __syncthreads();
        }
        #pragma unroll
        for (int si = 0; si < 4; si++) {
            size_t row = (size_t)(b0 + sc + si) * 129 + 1 + k0;
            #pragma unroll
            for (int u = 0; u < 8; u++) out[row + u] = fmaxf(acc[si][u], 0.f);
        }
    }
}

// ---------------- launch ----------------
extern "C" void kernel_launch(void* const* d_in, const int* in_sizes, int n_in,
                              void* d_out, int out_size) {
    const float* x   = (const float*)d_in[0];
    const float* emb = (const float*)d_in[1];
    const float* Wc  = (const float*)d_in[2];
    const float* bc  = (const float*)d_in[3];
    const float* Wf  = (const float*)d_in[4];
    const float* bf  = (const float*)d_in[5];
    const float* W1  = (const float*)d_in[6];
    const float* b1  = (const float*)d_in[7];
    const float* W2  = (const float*)d_in[8];
    const float* b2  = (const float*)d_in[9];
    float* out = (float*)d_out;

    prep_A1<<<256, 64>>>(emb, Wc, bc, W1, b1);
    prep_W2T<<<128, 256>>>(W2);
    cudaFuncSetAttribute(deepfm_main, cudaFuncAttributeMaxDynamicSharedMemorySize, SMEM_BYTES);
    deepfm_main<<<65536 / TB, 256, SMEM_BYTES>>>(x, emb, Wc, bc, Wf, bf, b2, out);
}

// round 2
// speedup vs baseline: 2.1853x; 2.1853x over previous
#include <cuda_runtime.h>

// ---------------- constants ----------------
#define TB    64            // samples per block
#define PADX  72            // xs row pad
#define PADH  264           // h1s row pad
#define PADW  132           // ws row pad
#define SM_X  (64*PADX)     // 4608 floats
#define SM_A  16896         // a1s [64][264] tf32  (reused as ws [128][132])
#define SM_H  (64*PADH)     // 16896 floats
#define SM_E  1984          // emb tables 62*2*16
#define SMEM_FLOATS (SM_X + SM_A + SM_H + SM_E)   // 40384
#define SMEM_BYTES  (SMEM_FLOATS * 4)             // 161536 B

// device scratch (no allocation allowed)
__device__ float g_A1T[64 * 256];   // A1 transposed [f][j], tf32-rounded
__device__ float g_c1[256];         // W1@base + b1  (fp32)
__device__ float g_W2T[256 * 128];  // W2 transposed [i][k], tf32-rounded

__device__ __forceinline__ unsigned tf32r(float f) {
    unsigned u;
    asm("cvt.rna.tf32.f32 %0, %1;" : "=r"(u) : "f"(f));
    return u;
}

__device__ __forceinline__ void mma_tf32(float& c0, float& c1, float& c2, float& c3,
                                         unsigned a0, unsigned a1, unsigned a2, unsigned a3,
                                         unsigned b0, unsigned b1) {
    asm volatile("mma.sync.aligned.m16n8k8.row.col.f32.tf32.tf32.f32 "
                 "{%0,%1,%2,%3}, {%4,%5,%6,%7}, {%8,%9}, {%0,%1,%2,%3};"
                 : "+f"(c0), "+f"(c1), "+f"(c2), "+f"(c3)
                 : "r"(a0), "r"(a1), "r"(a2), "r"(a3), "r"(b0), "r"(b1));
}

// ---------------- prep: A1^T (tf32) + c1 ----------------
__global__ void prep_A1T(const float* __restrict__ emb, const float* __restrict__ Wc,
                         const float* __restrict__ bc,  const float* __restrict__ W1,
                         const float* __restrict__ b1) {
    int f = threadIdx.x & 63;
    int j = blockIdx.x * 4 + (threadIdx.x >> 6);
    const float* w = W1 + j * 1024;
    float af = 0.f, cpart = 0.f;
    if (f < 62) {
        #pragma unroll
        for (int d = 0; d < 16; d++) {
            float wv = w[f * 16 + d];
            float e0 = emb[f * 32 + d];
            float e1 = emb[f * 32 + 16 + d];
            af    += wv * (e1 - e0);
            cpart += wv * e0;
        }
    } else {
        int jc = f - 62;
        #pragma unroll
        for (int m = 0; m < 32; m++) {
            float wv = w[992 + m];
            af += wv * Wc[m * 2 + jc];
            if (jc == 0) cpart += wv * bc[m];
        }
    }
    g_A1T[f * 256 + j] = __uint_as_float(tf32r(af));
    __shared__ float red[256];
    red[threadIdx.x] = cpart;
    __syncthreads();
    if (f == 0) {
        float s = b1[j];
        int base = threadIdx.x & 192;
        #pragma unroll
        for (int t = 0; t < 64; t++) s += red[base + t];
        g_c1[j] = s;
    }
}

// ---------------- prep: W2^T (tf32) ----------------
__global__ void prep_W2T(const float* __restrict__ W2) {
    int idx = blockIdx.x * 256 + threadIdx.x;  // 0..32767
    int i = idx >> 7, k = idx & 127;
    g_W2T[idx] = __uint_as_float(tf32r(W2[k * 256 + i]));
}

// ---------------- fused main kernel ----------------
__global__ __launch_bounds__(256, 1) void deepfm_main(
    const float* __restrict__ x,   const float* __restrict__ emb,
    const float* __restrict__ Wc,  const float* __restrict__ bc,
    const float* __restrict__ Wf,  const float* __restrict__ bf,
    const float* __restrict__ b2,  float* __restrict__ out) {
    extern __shared__ float sm[];
    float* xs  = sm;                    // [64 s][PADX]
    float* a1s = sm + SM_X;             // [64 f][264]  (later: ws [128][132])
    float* h1s = sm + SM_X + SM_A;      // [64 s][PADH]
    float* es  = sm + SM_X + SM_A + SM_H;

    const int tid = threadIdx.x;
    const int b0  = blockIdx.x * TB;
    const float* xblk = x + (size_t)b0 * 64;

    // ---- stage x, A1T, emb ----
    #pragma unroll
    for (int r = 0; r < 16; r++) {
        int lin = r * 256 + tid;
        xs[(lin >> 6) * PADX + (lin & 63)] = xblk[lin];
    }
    #pragma unroll
    for (int r = 0; r < 64; r++) {
        int lin = r * 256 + tid;       // f = lin>>8, j = lin&255
        a1s[(lin >> 8) * 264 + (lin & 255)] = g_A1T[lin];
    }
    for (int idx = tid; idx < SM_E; idx += 256) es[idx] = emb[idx];
    __syncthreads();

    // ---- FM phase (fp32 exact): 4 threads/sample ----
    {
        int s = tid >> 2, u = tid & 3;
        const float* xr = xs + s * PADX;
        float se0 = 0.f, se1 = 0.f, se2 = 0.f, se3 = 0.f, ssq = 0.f, first = 0.f;
        for (int f = 0; f < 62; f++) {
            float xv = xr[f];
            int off = f * 32 + (xv > 0.5f ? 16 : 0) + u * 4;
            float v0 = es[off], v1 = es[off + 1], v2 = es[off + 2], v3 = es[off + 3];
            se0 += v0; se1 += v1; se2 += v2; se3 += v3;
            ssq += v0 * v0 + v1 * v1 + v2 * v2 + v3 * v3;
        }
        float x62 = xr[62], x63 = xr[63];
        #pragma unroll
        for (int c = 0; c < 2; c++) {
            #pragma unroll
            for (int dd = 0; dd < 4; dd++) {
                int m = c * 16 + u * 4 + dd;
                float v = __ldg(&bc[m]) + x62 * __ldg(&Wc[m * 2]) + x63 * __ldg(&Wc[m * 2 + 1]);
                if (dd == 0) se0 += v; else if (dd == 1) se1 += v;
                else if (dd == 2) se2 += v; else se3 += v;
                ssq += v * v;
            }
        }
        #pragma unroll
        for (int ff = 0; ff < 16; ff++) {
            int f = u * 16 + ff;
            first += xr[f] * __ldg(&Wf[f]);
        }
        float part = se0 * se0 + se1 * se1 + se2 * se2 + se3 * se3;
        part  += __shfl_xor_sync(0xffffffffu, part, 1);
        part  += __shfl_xor_sync(0xffffffffu, part, 2);
        ssq   += __shfl_xor_sync(0xffffffffu, ssq, 1);
        ssq   += __shfl_xor_sync(0xffffffffu, ssq, 2);
        first += __shfl_xor_sync(0xffffffffu, first, 1);
        first += __shfl_xor_sync(0xffffffffu, first, 2);
        if (u == 0)
            out[(size_t)(b0 + s) * 129] = first + __ldg(&bf[0]) + 0.5f * (part - ssq);
    }

    const int w = tid >> 5, lane = tid & 31;
    const int g = lane >> 2, tg = lane & 3;

    // ---- Phase B (tf32 mma): z1[64s x 256j] = x @ A1T + c1, relu -> h1s ----
    {
        const int mrow = w & 3, nh = w >> 2;
        const int sB = mrow * 16;
        float acc[16][4];
        #pragma unroll
        for (int t = 0; t < 16; t++) {
            int j0 = nh * 128 + t * 8;
            float cv0 = g_c1[j0 + 2 * tg], cv1 = g_c1[j0 + 2 * tg + 1];
            acc[t][0] = cv0; acc[t][1] = cv1; acc[t][2] = cv0; acc[t][3] = cv1;
        }
        #pragma unroll
        for (int k0 = 0; k0 < 64; k0 += 8) {
            unsigned a0 = __float_as_uint(xs[(sB + g) * PADX + k0 + tg]);        // x exact in tf32
            unsigned a1 = __float_as_uint(xs[(sB + g + 8) * PADX + k0 + tg]);
            unsigned a2 = __float_as_uint(xs[(sB + g) * PADX + k0 + tg + 4]);
            unsigned a3 = __float_as_uint(xs[(sB + g + 8) * PADX + k0 + tg + 4]);
            #pragma unroll
            for (int t = 0; t < 16; t++) {
                int j0 = nh * 128 + t * 8;
                unsigned bb0 = __float_as_uint(a1s[(k0 + tg) * 264 + j0 + g]);
                unsigned bb1 = __float_as_uint(a1s[(k0 + tg + 4) * 264 + j0 + g]);
                mma_tf32(acc[t][0], acc[t][1], acc[t][2], acc[t][3], a0, a1, a2, a3, bb0, bb1);
            }
        }
        #pragma unroll
        for (int t = 0; t < 16; t++) {
            int j0 = nh * 128 + t * 8 + 2 * tg;
            h1s[(sB + g) * PADH + j0]         = fmaxf(acc[t][0], 0.f);
            h1s[(sB + g) * PADH + j0 + 1]     = fmaxf(acc[t][1], 0.f);
            h1s[(sB + g + 8) * PADH + j0]     = fmaxf(acc[t][2], 0.f);
            h1s[(sB + g + 8) * PADH + j0 + 1] = fmaxf(acc[t][3], 0.f);
        }
    }
    __syncthreads();

    // ---- Phase C (tf32 mma): out2[64s x 128k] = relu(h1 @ W2T + b2) ----
    {
        const int mrow = w & 3, nh = w >> 2;
        const int sB = mrow * 16;
        float acc[8][4];
        #pragma unroll
        for (int t = 0; t < 8; t++) {
            int k0 = nh * 64 + t * 8;
            float bv0 = __ldg(&b2[k0 + 2 * tg]), bv1 = __ldg(&b2[k0 + 2 * tg + 1]);
            acc[t][0] = bv0; acc[t][1] = bv1; acc[t][2] = bv0; acc[t][3] = bv1;
        }
        float* ws = a1s;   // reuse A1T region as W2T chunk [128][132]
        #pragma unroll 1
        for (int half = 0; half < 2; half++) {
            #pragma unroll
            for (int r = 0; r < 64; r++) {
                int lin = r * 256 + tid;   // i = lin>>7, k = lin&127
                ws[(lin >> 7) * PADW + (lin & 127)] = g_W2T[half * 16384 + lin];
            }
            __syncthreads();
            #pragma unroll
            for (int kk = 0; kk < 128; kk += 8) {
                int i = half * 128 + kk;
                unsigned a0 = tf32r(h1s[(sB + g) * PADH + i + tg]);
                unsigned a1 = tf32r(h1s[(sB + g + 8) * PADH + i + tg]);
                unsigned a2 = tf32r(h1s[(sB + g) * PADH + i + tg + 4]);
                unsigned a3 = tf32r(h1s[(sB + g + 8) * PADH + i + tg + 4]);
                #pragma unroll
                for (int t = 0; t < 8; t++) {
                    int k0 = nh * 64 + t * 8;
                    unsigned bb0 = __float_as_uint(ws[(kk + tg) * PADW + k0 + g]);
                    unsigned bb1 = __float_as_uint(ws[(kk + tg + 4) * PADW + k0 + g]);
                    mma_tf32(acc[t][0], acc[t][1], acc[t][2], acc[t][3], a0, a1, a2, a3, bb0, bb1);
                }
            }
            __syncthreads();
        }
        #pragma unroll
        for (int t = 0; t < 8; t++) {
            int k0 = nh * 64 + t * 8 + 2 * tg;
            size_t r0 = (size_t)(b0 + sB + g) * 129 + 1 + k0;
            size_t r1 = (size_t)(b0 + sB + g + 8) * 129 + 1 + k0;
            out[r0]     = fmaxf(acc[t][0], 0.f);
            out[r0 + 1] = fmaxf(acc[t][1], 0.f);
            out[r1]     = fmaxf(acc[t][2], 0.f);
            out[r1 + 1] = fmaxf(acc[t][3], 0.f);
        }
    }
}

// ---------------- launch ----------------
extern "C" void kernel_launch(void* const* d_in, const int* in_sizes, int n_in,
                              void* d_out, int out_size) {
    const float* x   = (const float*)d_in[0];
    const float* emb = (const float*)d_in[1];
    const float* Wc  = (const float*)d_in[2];
    const float* bc  = (const float*)d_in[3];
    const float* Wf  = (const float*)d_in[4];
    const float* bf  = (const float*)d_in[5];
    const float* W1  = (const float*)d_in[6];
    const float* b1  = (const float*)d_in[7];
    const float* W2  = (const float*)d_in[8];
    const float* b2  = (const float*)d_in[9];
    float* out = (float*)d_out;

    prep_A1T<<<64, 256>>>(emb, Wc, bc, W1, b1);
    prep_W2T<<<128, 256>>>(W2);
    cudaFuncSetAttribute(deepfm_main, cudaFuncAttributeMaxDynamicSharedMemorySize, SMEM_BYTES);
    deepfm_main<<<65536 / TB, 256, SMEM_BYTES>>>(x, emb, Wc, bc, Wf, bf, b2, out);
}

// round 3
// speedup vs baseline: 2.7707x; 1.2679x over previous
#include <cuda_runtime.h>

// ---------------- geometry ----------------
#define TB     64
#define PADX   68                     // xs row pad (floats)
#define PADH   72                     // h1sT row pad (floats)
#define NJT    40                     // 320 cols / 8
#define SM_XS  (64 * PADX)            // 4352
#define SM_A1  (8 * NJT * 64)        // 20480 floats (frag order)
#define SM_H   (256 * PADH)           // 18432
#define SM_WF  8192                   // one W2 sub-chunk (8 i-tiles)
#define SMEM_FLOATS (SM_XS + SM_A1 + SM_H + SM_WF)   // 51456
#define SMEM_BYTES  (SMEM_FLOATS * 4)                // 205824

// device scratch
__device__ float g_A1pack[8 * NJT * 64];   // GEMM1 B-fragments (tf32 bits), 320 cols incl Q
__device__ float g_W2pack[32 * 16 * 64];   // GEMM2 B-fragments (tf32 bits)
__device__ float g_c1[256];                // z1 bias
__device__ float g_c0[1];                  // FM constant (bf + alpha2)

__device__ __forceinline__ unsigned tf32r(float f) {
    unsigned u; asm("cvt.rna.tf32.f32 %0, %1;" : "=r"(u) : "f"(f)); return u;
}
__device__ __forceinline__ void mma_tf32(float& c0, float& c1, float& c2, float& c3,
                                         unsigned a0, unsigned a1, unsigned a2, unsigned a3,
                                         unsigned b0, unsigned b1) {
    asm volatile("mma.sync.aligned.m16n8k8.row.col.f32.tf32.tf32.f32 "
                 "{%0,%1,%2,%3}, {%4,%5,%6,%7}, {%8,%9}, {%0,%1,%2,%3};"
                 : "+f"(c0), "+f"(c1), "+f"(c2), "+f"(c3)
                 : "r"(a0), "r"(a1), "r"(a2), "r"(a3), "r"(b0), "r"(b1));
}

// pack index for GEMM1 B matrix element Bmat[k=f][col j] (f<64, j<320)
__device__ __forceinline__ int a1_pidx(int f, int j) {
    return ((f >> 3) * NJT + (j >> 3)) * 64 + ((j & 7) * 4 + (f & 3)) * 2 + ((f >> 2) & 1);
}

// ---------------- prep 1: A1 columns (j<256) + c1 ----------------
__global__ void prep_A1(const float* __restrict__ emb, const float* __restrict__ Wc,
                        const float* __restrict__ bc,  const float* __restrict__ W1,
                        const float* __restrict__ b1) {
    int j = blockIdx.x, f = threadIdx.x;
    const float* w = W1 + j * 1024;
    float af = 0.f, cpart = 0.f;
    if (f < 62) {
        #pragma unroll
        for (int d = 0; d < 16; d++) {
            float wv = w[f * 16 + d];
            af    += wv * (emb[f * 32 + 16 + d] - emb[f * 32 + d]);
            cpart += wv * emb[f * 32 + d];
        }
    } else {
        int jc = f - 62;
        #pragma unroll
        for (int m = 0; m < 32; m++) {
            float wv = w[992 + m];
            af += wv * Wc[m * 2 + jc];
            if (jc == 0) cpart += wv * bc[m];
        }
    }
    g_A1pack[a1_pidx(f, j)] = __uint_as_float(tf32r(af));
    __shared__ float red[64];
    red[f] = cpart;
    __syncthreads();
    if (f == 0) {
        float s = b1[j];
        #pragma unroll
        for (int t = 0; t < 64; t++) s += red[t];
        g_c1[j] = s;
    }
}

// ---------------- prep 2: W2 fragments ----------------
__global__ void prep_W2(const float* __restrict__ W2) {
    int e = blockIdx.x * 256 + threadIdx.x;       // 0..16383
    int it = e >> 9, kt = (e >> 5) & 15, lane = e & 31;
    int g = lane >> 2, tg = lane & 3;
    int i = it * 8 + tg, k = kt * 8 + g;
    float2 v;
    v.x = __uint_as_float(tf32r(W2[k * 256 + i]));
    v.y = __uint_as_float(tf32r(W2[k * 256 + i + 4]));
    ((float2*)g_W2pack)[e] = v;
}

// ---------------- prep 3: FM quadratic form Q + C0 ----------------
__global__ void prep_Q(const float* __restrict__ emb, const float* __restrict__ Wc,
                       const float* __restrict__ bc,  const float* __restrict__ Wf,
                       const float* __restrict__ bf) {
    __shared__ float v[64][16], u[16], tS[64], sS[64], Rs[1];
    int tid = threadIdx.x;
    for (int idx = tid; idx < 1024; idx += 256) {
        int f = idx >> 4, d = idx & 15;
        float val;
        if (f < 62)       val = emb[f * 32 + 16 + d] - emb[f * 32 + d];
        else if (f == 62) val = Wc[d * 2]     + Wc[(16 + d) * 2];
        else              val = Wc[d * 2 + 1] + Wc[(16 + d) * 2 + 1];
        v[f][d] = val;
    }
    if (tid < 16) {
        float s = bc[tid] + bc[16 + tid];
        for (int f = 0; f < 62; f++) s += emb[f * 32 + tid];
        u[tid] = s;
    }
    if (tid == 0) {
        float r = 0.f;
        for (int m = 0; m < 32; m++) r += Wc[m * 2] * Wc[m * 2 + 1];
        Rs[0] = r;
    }
    __syncthreads();
    if (tid < 64) {
        float t = 0.f, s = 0.f;
        if (tid < 62) {
            #pragma unroll
            for (int d = 0; d < 16; d++) { t += emb[tid * 32 + d] * v[tid][d]; s += v[tid][d] * v[tid][d]; }
        } else {
            int jc = tid - 62;
            for (int m = 0; m < 32; m++) { float wv = Wc[m * 2 + jc]; t += bc[m] * wv; s += wv * wv; }
        }
        tS[tid] = t; sS[tid] = s;
    }
    __syncthreads();
    // Q entries: 4096 total over 8 blocks
    for (int r = 0; r < 2; r++) {
        int p = blockIdx.x * 512 + r * 256 + tid;
        int fr = p >> 6, gc = p & 63;
        float q;
        if (fr == gc) {
            float uv = 0.f, vv = 0.f;
            #pragma unroll
            for (int d = 0; d < 16; d++) { uv += u[d] * v[fr][d]; vv += v[fr][d] * v[fr][d]; }
            q = uv - tS[fr] + 0.5f * (vv - sS[fr]) + Wf[fr];
        } else {
            float dp = 0.f;
            #pragma unroll
            for (int d = 0; d < 16; d++) dp += v[fr][d] * v[gc][d];
            float rr = ((fr == 62 && gc == 63) || (fr == 63 && gc == 62)) ? Rs[0] : 0.f;
            q = 0.5f * (dp - rr);
        }
        g_A1pack[a1_pidx(fr, 256 + gc)] = __uint_as_float(tf32r(q));
    }
    if (blockIdx.x == 0 && tid == 0) {
        float uu = 0.f;
        for (int d = 0; d < 16; d++) uu += u[d] * u[d];
        float e2 = 0.f;
        for (int f = 0; f < 62; f++)
            for (int d = 0; d < 16; d++) { float e = emb[f * 32 + d]; e2 += e * e; }
        for (int m = 0; m < 32; m++) e2 += bc[m] * bc[m];
        g_c0[0] = bf[0] + 0.5f * (uu - e2);
    }
}

// ---------------- fused main kernel ----------------
__global__ __launch_bounds__(256, 1) void deepfm_main(
    const float* __restrict__ x, const float* __restrict__ b2, float* __restrict__ out) {
    extern __shared__ float sm[];
    float* xs  = sm;                         // [64][PADX]
    float* a1f = sm + SM_XS;                 // frag-order GEMM1 B (20480)
    float* h1T = sm + SM_XS + SM_A1;         // [256 i][PADH s] tf32 bits
    float* wf  = sm + SM_XS + SM_A1 + SM_H;  // W2 frag sub-chunk (8192)

    const int tid = threadIdx.x;
    const int b0  = blockIdx.x * TB;
    const float* xblk = x + (size_t)b0 * 64;

    // stage x (coalesced -> padded rows) and GEMM1 fragments (linear copy)
    #pragma unroll
    for (int r = 0; r < 16; r++) {
        int lin = r * 256 + tid;
        xs[(lin >> 6) * PADX + (lin & 63)] = xblk[lin];
    }
    {
        const float4* src = (const float4*)g_A1pack;
        float4* dst = (float4*)a1f;
        #pragma unroll
        for (int r = 0; r < 20; r++) dst[r * 256 + tid] = __ldg(&src[r * 256 + tid]);
    }
    __syncthreads();

    const int w = tid >> 5, lane = tid & 31, g = lane >> 2, tg = lane & 3;
    const int mrow = w & 3, nh = w >> 2, sB = mrow * 16;

    // ---- GEMM1: z[64 x 320] = x @ [A1 | Q] ----
    unsigned af[8][4];
    #pragma unroll
    for (int k0 = 0; k0 < 8; k0++) {
        int base = (sB + g) * PADX + k0 * 8 + tg;
        af[k0][0] = __float_as_uint(xs[base]);
        af[k0][1] = __float_as_uint(xs[base + 8 * PADX]);
        af[k0][2] = __float_as_uint(xs[base + 4]);
        af[k0][3] = __float_as_uint(xs[base + 8 * PADX + 4]);
    }
    float acc[20][4];
    #pragma unroll
    for (int t = 0; t < 20; t++) {
        int j0 = (nh * 20 + t) * 8;
        float c0v = 0.f, c1v = 0.f;
        if (j0 < 256) { c0v = __ldg(&g_c1[j0 + 2 * tg]); c1v = __ldg(&g_c1[j0 + 2 * tg + 1]); }
        acc[t][0] = c0v; acc[t][1] = c1v; acc[t][2] = c0v; acc[t][3] = c1v;
    }
    #pragma unroll
    for (int k0 = 0; k0 < 8; k0++) {
        const float2* bp = (const float2*)a1f + (k0 * NJT + nh * 20) * 32 + lane;
        #pragma unroll
        for (int t = 0; t < 20; t++) {
            float2 b = bp[t * 32];
            mma_tf32(acc[t][0], acc[t][1], acc[t][2], acc[t][3],
                     af[k0][0], af[k0][1], af[k0][2], af[k0][3],
                     __float_as_uint(b.x), __float_as_uint(b.y));
        }
    }
    // epilogue: h cols -> relu+tf32 -> h1T ; y cols -> FM dot
    #pragma unroll
    for (int t = 0; t < 20; t++) {
        int j0 = (nh * 20 + t) * 8;
        if (j0 < 256) {
            int jj = j0 + 2 * tg;
            h1T[jj * PADH + sB + g]           = __uint_as_float(tf32r(fmaxf(acc[t][0], 0.f)));
            h1T[(jj + 1) * PADH + sB + g]     = __uint_as_float(tf32r(fmaxf(acc[t][1], 0.f)));
            h1T[jj * PADH + sB + g + 8]       = __uint_as_float(tf32r(fmaxf(acc[t][2], 0.f)));
            h1T[(jj + 1) * PADH + sB + g + 8] = __uint_as_float(tf32r(fmaxf(acc[t][3], 0.f)));
        }
    }
    if (nh == 1) {   // FM: out0 = C0 + sum_f x[s][f] * y[s][f]
        float d0 = 0.f, d1 = 0.f;
        #pragma unroll
        for (int t = 12; t < 20; t++) {
            int f0 = (t - 12) * 8 + 2 * tg;
            float2 xv0 = *(const float2*)&xs[(sB + g) * PADX + f0];
            float2 xv1 = *(const float2*)&xs[(sB + g + 8) * PADX + f0];
            d0 += xv0.x * acc[t][0] + xv0.y * acc[t][1];
            d1 += xv1.x * acc[t][2] + xv1.y * acc[t][3];
        }
        d0 += __shfl_xor_sync(0xffffffffu, d0, 1);
        d0 += __shfl_xor_sync(0xffffffffu, d0, 2);
        d1 += __shfl_xor_sync(0xffffffffu, d1, 1);
        d1 += __shfl_xor_sync(0xffffffffu, d1, 2);
        if (tg == 0) {
            float C0 = __ldg(&g_c0[0]);
            out[(size_t)(b0 + sB + g) * 129]     = C0 + d0;
            out[(size_t)(b0 + sB + g + 8) * 129] = C0 + d1;
        }
    }

    // ---- GEMM2: out[:,1:] = relu(h1 @ W2T + b2) ----
    float acc2[8][4];
    #pragma unroll
    for (int t = 0; t < 8; t++) {
        int k0 = nh * 64 + t * 8;
        float b0v = __ldg(&b2[k0 + 2 * tg]), b1v = __ldg(&b2[k0 + 2 * tg + 1]);
        acc2[t][0] = b0v; acc2[t][1] = b1v; acc2[t][2] = b0v; acc2[t][3] = b1v;
    }
    #pragma unroll 1
    for (int sc = 0; sc < 4; sc++) {
        __syncthreads();   // first iter: h1T ready barrier; later: protect wf reuse
        {
            const float4* src = (const float4*)g_W2pack + sc * 2048;
            float4* dst = (float4*)wf;
            #pragma unroll
            for (int r = 0; r < 8; r++) dst[r * 256 + tid] = __ldg(&src[r * 256 + tid]);
        }
        __syncthreads();
        #pragma unroll
        for (int itl = 0; itl < 8; itl++) {
            int i0 = sc * 64 + itl * 8;
            int base = (i0 + tg) * PADH + sB + g;
            unsigned a0 = __float_as_uint(h1T[base]);
            unsigned a1 = __float_as_uint(h1T[base + 8]);
            unsigned a2 = __float_as_uint(h1T[base + 4 * PADH]);
            unsigned a3 = __float_as_uint(h1T[base + 4 * PADH + 8]);
            const float2* bp = (const float2*)wf + (itl * 16 + nh * 8) * 32 + lane;
            #pragma unroll
            for (int t = 0; t < 8; t++) {
                float2 b = bp[t * 32];
                mma_tf32(acc2[t][0], acc2[t][1], acc2[t][2], acc2[t][3],
                         a0, a1, a2, a3, __float_as_uint(b.x), __float_as_uint(b.y));
            }
        }
    }
    #pragma unroll
    for (int t = 0; t < 8; t++) {
        int k0 = nh * 64 + t * 8 + 2 * tg;
        size_t r0 = (size_t)(b0 + sB + g) * 129 + 1 + k0;
        size_t r1 = (size_t)(b0 + sB + g + 8) * 129 + 1 + k0;
        out[r0]     = fmaxf(acc2[t][0], 0.f);
        out[r0 + 1] = fmaxf(acc2[t][1], 0.f);
        out[r1]     = fmaxf(acc2[t][2], 0.f);
        out[r1 + 1] = fmaxf(acc2[t][3], 0.f);
    }
}

// ---------------- launch ----------------
extern "C" void kernel_launch(void* const* d_in, const int* in_sizes, int n_in,
                              void* d_out, int out_size) {
    const float* x   = (const float*)d_in[0];
    const float* emb = (const float*)d_in[1];
    const float* Wc  = (const float*)d_in[2];
    const float* bc  = (const float*)d_in[3];
    const float* Wf  = (const float*)d_in[4];
    const float* bf  = (const float*)d_in[5];
    const float* W1  = (const float*)d_in[6];
    const float* b1  = (const float*)d_in[7];
    const float* W2  = (const float*)d_in[8];
    const float* b2  = (const float*)d_in[9];
    float* out = (float*)d_out;

    prep_A1<<<256, 64>>>(emb, Wc, bc, W1, b1);
    prep_W2<<<64, 256>>>(W2);
    prep_Q<<<8, 256>>>(emb, Wc, bc, Wf, bf);
    cudaFuncSetAttribute(deepfm_main, cudaFuncAttributeMaxDynamicSharedMemorySize, SMEM_BYTES);
    deepfm_main<<<65536 / TB, 256, SMEM_BYTES>>>(x, b2, out);
}

// round 4
// speedup vs baseline: 3.6214x; 1.3070x over previous
#include <cuda_runtime.h>
#include <cuda_fp16.h>

// ---------------- smem layout (u32 units) ----------------
// xs  : 64 rows x 72 halves  = 2304 u32   (x tile, fp16)
// b1f : GEMM1 B fragments     = 10240 u32  (4 kt x 40 nt x 32 lane x 2)
// h1  : 64 rows x 264 halves = 8448 u32   (relu(z1), fp16)
// wf  : W2 fragment chunk     = 4096 u32   (4 it x 16 nt x 32 x 2)
#define OFF_B1F 2304
#define OFF_H1  12544
#define OFF_WF  20992
#define SMEM_U32 25088
#define SMEM_BYTES (SMEM_U32 * 4)   // 100352

// device scratch
__device__ unsigned g_A1pack[10240];   // GEMM1 B frags (fp16x2): [A1 | Q], 320 cols
__device__ unsigned g_W2pack[16384];   // GEMM2 B frags (fp16x2)
__device__ float    g_c1[256];
__device__ float    g_c0[1];

__device__ __forceinline__ unsigned pack_h2(float a, float b) {
    __half2 h = __floats2half2_rn(a, b);
    return *(unsigned*)&h;
}
__device__ __forceinline__ void mma_fp16(float* c, unsigned a0, unsigned a1,
                                         unsigned a2, unsigned a3,
                                         unsigned b0, unsigned b1) {
    asm volatile("mma.sync.aligned.m16n8k16.row.col.f32.f16.f16.f32 "
                 "{%0,%1,%2,%3}, {%4,%5,%6,%7}, {%8,%9}, {%0,%1,%2,%3};"
                 : "+f"(c[0]), "+f"(c[1]), "+f"(c[2]), "+f"(c[3])
                 : "r"(a0), "r"(a1), "r"(a2), "r"(a3), "r"(b0), "r"(b1));
}
__device__ __forceinline__ void ldsm_x4(unsigned& r0, unsigned& r1, unsigned& r2,
                                        unsigned& r3, unsigned saddr) {
    asm volatile("ldmatrix.sync.aligned.m8n8.x4.shared.b16 {%0,%1,%2,%3}, [%4];"
                 : "=r"(r0), "=r"(r1), "=r"(r2), "=r"(r3) : "r"(saddr));
}

// ---------------- prep: A1 frags + c1 (blocks 0..31), W2 frags (32..95) ----------------
__global__ void prep_w(const float* __restrict__ emb, const float* __restrict__ Wc,
                       const float* __restrict__ bc,  const float* __restrict__ W1,
                       const float* __restrict__ b1,  const float* __restrict__ W2) {
    int b = blockIdx.x, tid = threadIdx.x;
    if (b < 32) {
        int j = b * 8 + (tid >> 5), p = tid & 31, f0 = 2 * p;
        const float* wrow = W1 + j * 1024;
        float a0f = 0.f, a1f = 0.f, cp = 0.f;
        if (p < 31) {
            #pragma unroll
            for (int d = 0; d < 16; d++) {
                float w0 = wrow[f0 * 16 + d], w1 = wrow[(f0 + 1) * 16 + d];
                a0f += w0 * (emb[f0 * 32 + 16 + d] - emb[f0 * 32 + d]);
                a1f += w1 * (emb[(f0 + 1) * 32 + 16 + d] - emb[(f0 + 1) * 32 + d]);
                cp  += w0 * emb[f0 * 32 + d] + w1 * emb[(f0 + 1) * 32 + d];
            }
        } else {  // f=62,63 continuous
            #pragma unroll
            for (int m = 0; m < 32; m++) {
                float wv = wrow[992 + m];
                a0f += wv * Wc[m * 2];
                a1f += wv * Wc[m * 2 + 1];
                cp  += wv * bc[m];
            }
        }
        int kt = p >> 3, reg = (p >> 2) & 1, tgx = p & 3;
        g_A1pack[((kt * 40 + (j >> 3)) * 32 + (j & 7) * 4 + tgx) * 2 + reg] = pack_h2(a0f, a1f);
        #pragma unroll
        for (int o = 16; o; o >>= 1) cp += __shfl_xor_sync(0xffffffffu, cp, o);
        if (p == 0) g_c1[j] = cp + b1[j];
    } else {
        int e = (b - 32) * 256 + tid;                 // 0..16383
        int it = e >> 10, r = e & 1023, nt = r >> 6, q = r & 63, l = q >> 1, reg = q & 1;
        int gg = l >> 2, tgx = l & 3;
        int i = it * 16 + reg * 8 + 2 * tgx;
        const float* wr = W2 + (nt * 8 + gg) * 256 + i;
        g_W2pack[((it * 16 + nt) * 32 + l) * 2 + reg] = pack_h2(wr[0], wr[1]);
    }
}

// ---------------- prep: FM quadratic Q frags + C0 ----------------
__global__ void prep_q(const float* __restrict__ emb, const float* __restrict__ Wc,
                       const float* __restrict__ bc,  const float* __restrict__ Wf,
                       const float* __restrict__ bf) {
    __shared__ float v[64][16], u[16], tS[64], sS[64], Rs[1];
    int tid = threadIdx.x;
    for (int idx = tid; idx < 1024; idx += 256) {
        int f = idx >> 4, d = idx & 15;
        float val;
        if (f < 62)       val = emb[f * 32 + 16 + d] - emb[f * 32 + d];
        else if (f == 62) val = Wc[d * 2]     + Wc[(16 + d) * 2];
        else              val = Wc[d * 2 + 1] + Wc[(16 + d) * 2 + 1];
        v[f][d] = val;
    }
    if (tid < 16) {
        float s = bc[tid] + bc[16 + tid];
        for (int f = 0; f < 62; f++) s += emb[f * 32 + tid];
        u[tid] = s;
    }
    if (tid == 0) {
        float r = 0.f;
        for (int m = 0; m < 32; m++) r += Wc[m * 2] * Wc[m * 2 + 1];
        Rs[0] = r;
    }
    __syncthreads();
    if (tid < 64) {
        float t = 0.f, s = 0.f;
        if (tid < 62) {
            #pragma unroll
            for (int d = 0; d < 16; d++) { t += emb[tid * 32 + d] * v[tid][d]; s += v[tid][d] * v[tid][d]; }
        } else {
            int jc = tid - 62;
            for (int m = 0; m < 32; m++) { float wv = Wc[m * 2 + jc]; t += bc[m] * wv; s += wv * wv; }
        }
        tS[tid] = t; sS[tid] = s;
    }
    __syncthreads();
    int e = blockIdx.x * 256 + tid;   // 0..2047, one u32 (2 Q rows) each
    int gc = e >> 5, p = e & 31, f0 = 2 * p;
    float q[2];
    #pragma unroll
    for (int h = 0; h < 2; h++) {
        int fr = f0 + h;
        if (fr == gc) {
            float uv = 0.f, vv = 0.f;
            #pragma unroll
            for (int d = 0; d < 16; d++) { uv += u[d] * v[fr][d]; vv += v[fr][d] * v[fr][d]; }
            q[h] = uv - tS[fr] + 0.5f * (vv - sS[fr]) + Wf[fr];
        } else {
            float dp = 0.f;
            #pragma unroll
            for (int d = 0; d < 16; d++) dp += v[fr][d] * v[gc][d];
            float rr = ((fr == 62 && gc == 63) || (fr == 63 && gc == 62)) ? Rs[0] : 0.f;
            q[h] = 0.5f * (dp - rr);
        }
    }
    int kt = p >> 3, reg = (p >> 2) & 1, tgx = p & 3;
    g_A1pack[((kt * 40 + 32 + (gc >> 3)) * 32 + (gc & 7) * 4 + tgx) * 2 + reg] = pack_h2(q[0], q[1]);
    if (blockIdx.x == 0 && tid == 0) {
        float uu = 0.f;
        for (int d = 0; d < 16; d++) uu += u[d] * u[d];
        float e2 = 0.f;
        for (int f = 0; f < 62; f++)
            for (int d = 0; d < 16; d++) { float ev = emb[f * 32 + d]; e2 += ev * ev; }
        for (int m = 0; m < 32; m++) e2 += bc[m] * bc[m];
        g_c0[0] = bf[0] + 0.5f * (uu - e2);
    }
}

// ---------------- fused main kernel ----------------
__global__ __launch_bounds__(256, 2) void deepfm_main(
    const float* __restrict__ x, const float* __restrict__ b2, float* __restrict__ out) {
    extern __shared__ unsigned smu[];
    __half*   xs  = (__half*)smu;              // [64][72]
    unsigned* b1f = smu + OFF_B1F;
    __half*   h1  = (__half*)(smu + OFF_H1);   // [64][264]
    unsigned* wfu = smu + OFF_WF;

    const int tid = threadIdx.x;
    const int b0  = blockIdx.x * 64;
    const float* xblk = x + (size_t)b0 * 64;

    // ---- stage x (fp32 -> fp16) ----
    {
        int s = tid >> 2, q = tid & 3;
        const float4* xr = (const float4*)(xblk + s * 64 + q * 16);
        float4 v0 = __ldg(xr), v1 = __ldg(xr + 1), v2 = __ldg(xr + 2), v3 = __ldg(xr + 3);
        __half2* dst = (__half2*)(xs + s * 72 + q * 16);
        dst[0] = __floats2half2_rn(v0.x, v0.y); dst[1] = __floats2half2_rn(v0.z, v0.w);
        dst[2] = __floats2half2_rn(v1.x, v1.y); dst[3] = __floats2half2_rn(v1.z, v1.w);
        dst[4] = __floats2half2_rn(v2.x, v2.y); dst[5] = __floats2half2_rn(v2.z, v2.w);
        dst[6] = __floats2half2_rn(v3.x, v3.y); dst[7] = __floats2half2_rn(v3.z, v3.w);
    }
    // ---- stage GEMM1 B fragments ----
    {
        const uint4* src = (const uint4*)g_A1pack;
        uint4* dst = (uint4*)b1f;
        #pragma unroll
        for (int r = 0; r < 10; r++) dst[r * 256 + tid] = __ldg(src + r * 256 + tid);
    }
    __syncthreads();

    const int w = tid >> 5, l = tid & 31, g = l >> 2, tg = l & 3;
    const int mrow = w & 3, nh = w >> 2, sB = mrow * 16;
    const int lrow = l & 15, lcol = l >> 4;

    unsigned xs_lm = (unsigned)__cvta_generic_to_shared(xs + (sB + lrow) * 72 + lcol * 8);
    unsigned h1_lm = (unsigned)__cvta_generic_to_shared(h1 + (sB + lrow) * 264 + lcol * 8);

    float fmd0 = 0.f, fmd1 = 0.f;

    // ---- GEMM1: z[64 x 320] = x @ [A1 | Q], two n-passes ----
    #pragma unroll 1
    for (int pass = 0; pass < 2; pass++) {
        int ntb = nh * 20 + pass * 10;
        float acc[10][4];
        #pragma unroll
        for (int t = 0; t < 10; t++) {
            int j0 = (ntb + t) * 8;
            float c0v = 0.f, c1v = 0.f;
            if (j0 < 256) { float2 cc = __ldg((const float2*)(g_c1 + j0 + 2 * tg)); c0v = cc.x; c1v = cc.y; }
            acc[t][0] = c0v; acc[t][1] = c1v; acc[t][2] = c0v; acc[t][3] = c1v;
        }
        #pragma unroll
        for (int kt = 0; kt < 4; kt++) {
            unsigned a0, a1, a2, a3;
            ldsm_x4(a0, a1, a2, a3, xs_lm + kt * 32);
            const uint2* bp = (const uint2*)b1f + (kt * 40 + ntb) * 32 + l;
            #pragma unroll
            for (int t = 0; t < 10; t++) {
                uint2 bb = bp[t * 32];
                mma_fp16(acc[t], a0, a1, a2, a3, bb.x, bb.y);
            }
        }
        #pragma unroll
        for (int t = 0; t < 10; t++) {
            int j0 = (ntb + t) * 8;
            if (j0 < 256) {
                *(__half2*)(h1 + (sB + g) * 264 + j0 + 2 * tg) =
                    __floats2half2_rn(fmaxf(acc[t][0], 0.f), fmaxf(acc[t][1], 0.f));
                *(__half2*)(h1 + (sB + g + 8) * 264 + j0 + 2 * tg) =
                    __floats2half2_rn(fmaxf(acc[t][2], 0.f), fmaxf(acc[t][3], 0.f));
            } else {
                int fo = j0 - 256;   // feature col base
                float2 xf0 = __half22float2(*(__half2*)(xs + (sB + g) * 72 + fo + 2 * tg));
                float2 xf1 = __half22float2(*(__half2*)(xs + (sB + g + 8) * 72 + fo + 2 * tg));
                fmd0 += xf0.x * acc[t][0] + xf0.y * acc[t][1];
                fmd1 += xf1.x * acc[t][2] + xf1.y * acc[t][3];
            }
        }
    }
    if (nh == 1) {   // FM output: out0 = C0 + x . (Q x)
        fmd0 += __shfl_xor_sync(0xffffffffu, fmd0, 1);
        fmd0 += __shfl_xor_sync(0xffffffffu, fmd0, 2);
        fmd1 += __shfl_xor_sync(0xffffffffu, fmd1, 1);
        fmd1 += __shfl_xor_sync(0xffffffffu, fmd1, 2);
        if (tg == 0) {
            float C0 = __ldg(&g_c0[0]);
            out[(size_t)(b0 + sB + g) * 129]     = C0 + fmd0;
            out[(size_t)(b0 + sB + g + 8) * 129] = C0 + fmd1;
        }
    }

    // ---- GEMM2: out[:,1:] = relu(h1 @ W2T + b2) ----
    float acc2[8][4];
    #pragma unroll
    for (int t = 0; t < 8; t++) {
        int k0 = nh * 64 + t * 8;
        float2 bb = __ldg((const float2*)(b2 + k0 + 2 * tg));
        acc2[t][0] = bb.x; acc2[t][1] = bb.y; acc2[t][2] = bb.x; acc2[t][3] = bb.y;
    }
    #pragma unroll 1
    for (int c = 0; c < 4; c++) {
        __syncthreads();   // c=0: h1 ready; later: protect wf reuse
        {
            const uint4* src = (const uint4*)g_W2pack + c * 1024;
            uint4* dst = (uint4*)wfu;
            #pragma unroll
            for (int r = 0; r < 4; r++) dst[r * 256 + tid] = __ldg(src + r * 256 + tid);
        }
        __syncthreads();
        #pragma unroll
        for (int itl = 0; itl < 4; itl++) {
            int it = c * 4 + itl;
            unsigned a0, a1, a2, a3;
            ldsm_x4(a0, a1, a2, a3, h1_lm + it * 32);
            const uint2* bp = (const uint2*)wfu + (itl * 16 + nh * 8) * 32 + l;
            #pragma unroll
            for (int t = 0; t < 8; t++) {
                uint2 bb = bp[t * 32];
                mma_fp16(acc2[t], a0, a1, a2, a3, bb.x, bb.y);
            }
        }
    }
    #pragma unroll
    for (int t = 0; t < 8; t++) {
        int k0 = nh * 64 + t * 8 + 2 * tg;
        size_t r0 = (size_t)(b0 + sB + g) * 129 + 1 + k0;
        size_t r1 = (size_t)(b0 + sB + g + 8) * 129 + 1 + k0;
        out[r0]     = fmaxf(acc2[t][0], 0.f);
        out[r0 + 1] = fmaxf(acc2[t][1], 0.f);
        out[r1]     = fmaxf(acc2[t][2], 0.f);
        out[r1 + 1] = fmaxf(acc2[t][3], 0.f);
    }
}

// ---------------- launch ----------------
extern "C" void kernel_launch(void* const* d_in, const int* in_sizes, int n_in,
                              void* d_out, int out_size) {
    const float* x   = (const float*)d_in[0];
    const float* emb = (const float*)d_in[1];
    const float* Wc  = (const float*)d_in[2];
    const float* bc  = (const float*)d_in[3];
    const float* Wf  = (const float*)d_in[4];
    const float* bf  = (const float*)d_in[5];
    const float* W1  = (const float*)d_in[6];
    const float* b1  = (const float*)d_in[7];
    const float* W2  = (const float*)d_in[8];
    const float* b2  = (const float*)d_in[9];
    float* out = (float*)d_out;

    prep_w<<<96, 256>>>(emb, Wc, bc, W1, b1, W2);
    prep_q<<<8, 256>>>(emb, Wc, bc, Wf, bf);
    cudaFuncSetAttribute(deepfm_main, cudaFuncAttributeMaxDynamicSharedMemorySize, SMEM_BYTES);
    deepfm_main<<<1024, 256, SMEM_BYTES>>>(x, b2, out);
}

// round 5
// speedup vs baseline: 4.8016x; 1.3259x over previous
#include <cuda_runtime.h>
#include <cuda_fp16.h>

// ---------------- smem layout (u32 units) ----------------
#define OFF_B1F 2304                 // xs: 64x72 halves = 2304 u32
#define OFF_H1  12544                // b1f: 10240 u32
#define OFF_WF  20992                // h1: 64x264 halves = 8448 u32
#define SMEM_U32 25088               // wf: 2 x 2048 u32
#define SMEM_BYTES (SMEM_U32 * 4)    // 100352

// device scratch
__device__ unsigned g_A1pack[10240];   // GEMM1 B frags (fp16x2): [A1 | Q], 320 cols
__device__ unsigned g_W2pack[16384];   // GEMM2 B frags (fp16x2), 8 chunks x 2048
__device__ float    g_c1[256];
__device__ float    g_c0[1];

__device__ __forceinline__ unsigned pack_h2(float a, float b) {
    __half2 h = __floats2half2_rn(a, b);
    return *(unsigned*)&h;
}
__device__ __forceinline__ void mma_fp16(float* c, unsigned a0, unsigned a1,
                                         unsigned a2, unsigned a3,
                                         unsigned b0, unsigned b1) {
    asm volatile("mma.sync.aligned.m16n8k16.row.col.f32.f16.f16.f32 "
                 "{%0,%1,%2,%3}, {%4,%5,%6,%7}, {%8,%9}, {%0,%1,%2,%3};"
                 : "+f"(c[0]), "+f"(c[1]), "+f"(c[2]), "+f"(c[3])
                 : "r"(a0), "r"(a1), "r"(a2), "r"(a3), "r"(b0), "r"(b1));
}
__device__ __forceinline__ void ldsm_x4(unsigned& r0, unsigned& r1, unsigned& r2,
                                        unsigned& r3, unsigned saddr) {
    asm volatile("ldmatrix.sync.aligned.m8n8.x4.shared.b16 {%0,%1,%2,%3}, [%4];"
                 : "=r"(r0), "=r"(r1), "=r"(r2), "=r"(r3) : "r"(saddr));
}
__device__ __forceinline__ void cp_async16(unsigned saddr, const void* gaddr) {
    asm volatile("cp.async.ca.shared.global [%0], [%1], 16;" :: "r"(saddr), "l"(gaddr));
}
__device__ __forceinline__ void cp_commit() { asm volatile("cp.async.commit_group;"); }

// =============== merged prep kernel: 48 blocks ===============
// b 0..31 : A1 frags + c1   (warp-per-row, coalesced W1 reads)
// b 32..39: W2 frags        (coalesced chunk staging)
// b 40..47: Q frags + C0
__global__ void prep_all(const float* __restrict__ emb, const float* __restrict__ Wc,
                         const float* __restrict__ bc,  const float* __restrict__ Wf,
                         const float* __restrict__ bf,  const float* __restrict__ W1,
                         const float* __restrict__ b1,  const float* __restrict__ W2) {
    __shared__ __align__(16) float shm[4160];
    int b = blockIdx.x, tid = threadIdx.x;

    if (b < 32) {
        float* dv   = shm;          // [1024]
        float* base = shm + 1024;   // [1024]
        float* WcA  = shm + 2048;   // [32]
        float* WcB  = shm + 2080;   // [32]
        for (int e = tid; e < 1024; e += 256) {
            int f = e >> 4, d = e & 15;
            if (f < 62) { dv[e] = emb[f * 32 + 16 + d] - emb[f * 32 + d]; base[e] = emb[f * 32 + d]; }
            else        { dv[e] = 0.f; base[e] = bc[e - 992]; }
        }
        if (tid < 32) { WcA[tid] = Wc[tid * 2]; WcB[tid] = Wc[tid * 2 + 1]; }
        __syncthreads();

        int w = tid >> 5, l = tid & 31;
        int j = b * 8 + w;
        const float4* wrow = (const float4*)(W1 + j * 1024);
        float cp = 0.f;
        #pragma unroll
        for (int r = 0; r < 8; r++) {
            int q = l + 32 * r;
            float4 wv = __ldg(wrow + q);
            int e0 = q * 4;
            float4 dvv = *(const float4*)(dv + e0);
            float4 bsv = *(const float4*)(base + e0);
            float pd = wv.x * dvv.x + wv.y * dvv.y + wv.z * dvv.z + wv.w * dvv.w;
            cp += wv.x * bsv.x + wv.y * bsv.y + wv.z * bsv.z + wv.w * bsv.w;
            pd += __shfl_xor_sync(0xffffffffu, pd, 1);
            pd += __shfl_xor_sync(0xffffffffu, pd, 2);
            float s62 = 0.f, s63 = 0.f;
            if (r == 7) {   // cont features 62/63 use all 32 W1 tail entries
                float p0 = 0.f, p1 = 0.f;
                if (l >= 24) {
                    int m0 = e0 - 992;
                    float4 wa = *(const float4*)(WcA + m0);
                    float4 wb = *(const float4*)(WcB + m0);
                    p0 = wv.x * wa.x + wv.y * wa.y + wv.z * wa.z + wv.w * wa.w;
                    p1 = wv.x * wb.x + wv.y * wb.y + wv.z * wb.z + wv.w * wb.w;
                }
                p0 += __shfl_xor_sync(0xffffffffu, p0, 1);
                p0 += __shfl_xor_sync(0xffffffffu, p0, 2);
                p0 += __shfl_xor_sync(0xffffffffu, p0, 4);
                p1 += __shfl_xor_sync(0xffffffffu, p1, 1);
                p1 += __shfl_xor_sync(0xffffffffu, p1, 2);
                p1 += __shfl_xor_sync(0xffffffffu, p1, 4);
                s62 = p0; s63 = p1;
            }
            float vnext = __shfl_sync(0xffffffffu, pd, (l + 4) & 31);
            int gidx = l >> 2;
            if ((l & 7) == 0) {
                float e0v = pd, e1v = vnext;
                if (r == 7 && gidx == 6) { e0v = s62; e1v = s63; }
                int p = (gidx >> 1) + 4 * r;           // pair index f/2
                int kt = p >> 3, reg = (p >> 2) & 1, tgx = p & 3;
                g_A1pack[((kt * 40 + (j >> 3)) * 32 + (j & 7) * 4 + tgx) * 2 + reg] =
                    pack_h2(e0v, e1v);
            }
        }
        #pragma unroll
        for (int o = 16; o; o >>= 1) cp += __shfl_xor_sync(0xffffffffu, cp, o);
        if (l == 0) g_c1[j] = cp + b1[j];

    } else if (b < 40) {
        int c = b - 32;
        float* w2s = shm;   // [128][32] cols [32c, 32c+32)
        for (int q = tid; q < 1024; q += 256) {
            int row = q >> 3, f4 = q & 7;
            *(float4*)(w2s + row * 32 + f4 * 4) =
                __ldg((const float4*)(W2 + row * 256 + c * 32 + f4 * 4));
        }
        __syncthreads();
        for (int e = tid; e < 2048; e += 256) {
            int reg = e & 1, l2 = (e >> 1) & 31, nt = (e >> 6) & 15, itl = e >> 10;
            int gg = l2 >> 2, tgx = l2 & 3;
            int il = itl * 16 + reg * 8 + 2 * tgx;
            int k  = nt * 8 + gg;
            g_W2pack[c * 2048 + e] = pack_h2(w2s[k * 32 + il], w2s[k * 32 + il + 1]);
        }

    } else {
        int qb = b - 40;
        float (*v)[16] = (float(*)[16])shm;
        float* u  = shm + 1024;
        float* tS = shm + 1040;
        float* sS = shm + 1104;
        float* Rs = shm + 1168;
        for (int idx = tid; idx < 1024; idx += 256) {
            int f = idx >> 4, d = idx & 15;
            float val;
            if (f < 62)       val = emb[f * 32 + 16 + d] - emb[f * 32 + d];
            else if (f == 62) val = Wc[d * 2]     + Wc[(16 + d) * 2];
            else              val = Wc[d * 2 + 1] + Wc[(16 + d) * 2 + 1];
            v[f][d] = val;
        }
        if (tid < 16) {
            float s = bc[tid] + bc[16 + tid];
            for (int f = 0; f < 62; f++) s += emb[f * 32 + tid];
            u[tid] = s;
        }
        if (tid == 0) {
            float r = 0.f;
            for (int m = 0; m < 32; m++) r += Wc[m * 2] * Wc[m * 2 + 1];
            Rs[0] = r;
        }
        __syncthreads();
        if (tid < 64) {
            float t = 0.f, s = 0.f;
            if (tid < 62) {
                #pragma unroll
                for (int d = 0; d < 16; d++) { t += emb[tid * 32 + d] * v[tid][d]; s += v[tid][d] * v[tid][d]; }
            } else {
                int jc = tid - 62;
                for (int m = 0; m < 32; m++) { float wv = Wc[m * 2 + jc]; t += bc[m] * wv; s += wv * wv; }
            }
            tS[tid] = t; sS[tid] = s;
        }
        __syncthreads();
        int e = qb * 256 + tid;
        int gc = e >> 5, p = e & 31, f0 = 2 * p;
        float q2[2];
        #pragma unroll
        for (int h = 0; h < 2; h++) {
            int fr = f0 + h;
            if (fr == gc) {
                float uv = 0.f, vv = 0.f;
                #pragma unroll
                for (int d = 0; d < 16; d++) { uv += u[d] * v[fr][d]; vv += v[fr][d] * v[fr][d]; }
                q2[h] = uv - tS[fr] + 0.5f * (vv - sS[fr]) + Wf[fr];
            } else {
                float dp = 0.f;
                #pragma unroll
                for (int d = 0; d < 16; d++) dp += v[fr][d] * v[gc][d];
                float rr = ((fr == 62 && gc == 63) || (fr == 63 && gc == 62)) ? Rs[0] : 0.f;
                q2[h] = 0.5f * (dp - rr);
            }
        }
        int kt = p >> 3, reg = (p >> 2) & 1, tgx = p & 3;
        g_A1pack[((kt * 40 + 32 + (gc >> 3)) * 32 + (gc & 7) * 4 + tgx) * 2 + reg] =
            pack_h2(q2[0], q2[1]);
        if (qb == 0 && tid == 0) {
            float uu = 0.f;
            for (int d = 0; d < 16; d++) uu += u[d] * u[d];
            float e2 = 0.f;
            for (int f = 0; f < 62; f++)
                for (int d = 0; d < 16; d++) { float ev = emb[f * 32 + d]; e2 += ev * ev; }
            for (int m = 0; m < 32; m++) e2 += bc[m] * bc[m];
            g_c0[0] = bf[0] + 0.5f * (uu - e2);
        }
    }
}

// =============== fused main kernel ===============
__global__ __launch_bounds__(256, 2) void deepfm_main(
    const float* __restrict__ x, const float* __restrict__ b2, float* __restrict__ out) {
    extern __shared__ unsigned smu[];
    __half*   xs  = (__half*)smu;              // [64][72]
    unsigned* b1f = smu + OFF_B1F;
    __half*   h1  = (__half*)(smu + OFF_H1);   // [64][264]
    unsigned* wfA = smu + OFF_WF;              // chunk buffers, 2048 u32 each
    unsigned* wfB = smu + OFF_WF + 2048;

    const int tid = threadIdx.x;
    const int b0  = blockIdx.x * 64;

    // stage b1f (group 0) and W2 chunk0 (group 1) via cp.async
    {
        unsigned dstb = (unsigned)__cvta_generic_to_shared(b1f) + tid * 16;
        const char* srcb = (const char*)g_A1pack + tid * 16;
        #pragma unroll
        for (int r = 0; r < 10; r++) cp_async16(dstb + r * 4096, srcb + r * 4096);
        cp_commit();
        unsigned dstw = (unsigned)__cvta_generic_to_shared(wfA) + tid * 16;
        const char* srcw = (const char*)g_W2pack + tid * 16;
        cp_async16(dstw, srcw);
        cp_async16(dstw + 4096, srcw + 4096);
        cp_commit();
    }
    // stage x (fp32 -> fp16)
    {
        int s = tid >> 2, q = tid & 3;
        const float4* xr = (const float4*)(x + (size_t)(b0 + s) * 64 + q * 16);
        float4 v0 = __ldg(xr), v1 = __ldg(xr + 1), v2 = __ldg(xr + 2), v3 = __ldg(xr + 3);
        __half2* dst = (__half2*)(xs + s * 72 + q * 16);
        dst[0] = __floats2half2_rn(v0.x, v0.y); dst[1] = __floats2half2_rn(v0.z, v0.w);
        dst[2] = __floats2half2_rn(v1.x, v1.y); dst[3] = __floats2half2_rn(v1.z, v1.w);
        dst[4] = __floats2half2_rn(v2.x, v2.y); dst[5] = __floats2half2_rn(v2.z, v2.w);
        dst[6] = __floats2half2_rn(v3.x, v3.y); dst[7] = __floats2half2_rn(v3.z, v3.w);
    }
    asm volatile("cp.async.wait_group 1;" ::: "memory");   // b1f ready (chunk0 may fly)
    __syncthreads();

    const int w = tid >> 5, l = tid & 31, g = l >> 2, tg = l & 3;
    const int mh = w & 1, nq = w >> 1;           // 2 m-halves x 4 n-quarters
    const int lrow = l & 15, lcol = l >> 4;
    const int rbase = mh * 32;

    unsigned xs_lm0 = (unsigned)__cvta_generic_to_shared(xs + (rbase + lrow) * 72 + lcol * 8);
    unsigned xs_lm1 = xs_lm0 + 16 * 72 * 2;
    unsigned h1_lm0 = (unsigned)__cvta_generic_to_shared(h1 + (rbase + lrow) * 264 + lcol * 8);
    unsigned h1_lm1 = h1_lm0 + 16 * 264 * 2;

    // ---- GEMM1: z[64 x 320] = x @ [A1 | Q] ----
    unsigned am[2][4][4];
    #pragma unroll
    for (int kt = 0; kt < 4; kt++) {
        ldsm_x4(am[0][kt][0], am[0][kt][1], am[0][kt][2], am[0][kt][3], xs_lm0 + kt * 32);
        ldsm_x4(am[1][kt][0], am[1][kt][1], am[1][kt][2], am[1][kt][3], xs_lm1 + kt * 32);
    }
    float fmd[2][2] = {{0.f, 0.f}, {0.f, 0.f}};
    const int ntb = nq * 10;
    #pragma unroll 1
    for (int pass = 0; pass < 2; pass++) {
        int nt0 = ntb + pass * 5;
        float acc[2][5][4];
        #pragma unroll
        for (int t = 0; t < 5; t++) {
            int j0 = (nt0 + t) * 8;
            float c0v = 0.f, c1v = 0.f;
            if (j0 < 256) { float2 cc = __ldg((const float2*)(g_c1 + j0 + 2 * tg)); c0v = cc.x; c1v = cc.y; }
            acc[0][t][0] = c0v; acc[0][t][1] = c1v; acc[0][t][2] = c0v; acc[0][t][3] = c1v;
            acc[1][t][0] = c0v; acc[1][t][1] = c1v; acc[1][t][2] = c0v; acc[1][t][3] = c1v;
        }
        #pragma unroll
        for (int kt = 0; kt < 4; kt++) {
            const uint2* bp = (const uint2*)b1f + (kt * 40 + nt0) * 32 + l;
            #pragma unroll
            for (int t = 0; t < 5; t++) {
                uint2 bb = bp[t * 32];
                mma_fp16(acc[0][t], am[0][kt][0], am[0][kt][1], am[0][kt][2], am[0][kt][3], bb.x, bb.y);
                mma_fp16(acc[1][t], am[1][kt][0], am[1][kt][1], am[1][kt][2], am[1][kt][3], bb.x, bb.y);
            }
        }
        #pragma unroll
        for (int t = 0; t < 5; t++) {
            int j0 = (nt0 + t) * 8;
            #pragma unroll
            for (int mt = 0; mt < 2; mt++) {
                int r0 = rbase + mt * 16 + g;
                if (j0 < 256) {
                    *(__half2*)(h1 + r0 * 264 + j0 + 2 * tg) =
                        __floats2half2_rn(fmaxf(acc[mt][t][0], 0.f), fmaxf(acc[mt][t][1], 0.f));
                    *(__half2*)(h1 + (r0 + 8) * 264 + j0 + 2 * tg) =
                        __floats2half2_rn(fmaxf(acc[mt][t][2], 0.f), fmaxf(acc[mt][t][3], 0.f));
                } else {
                    int fo = j0 - 256;
                    float2 xf0 = __half22float2(*(__half2*)(xs + r0 * 72 + fo + 2 * tg));
                    float2 xf1 = __half22float2(*(__half2*)(xs + (r0 + 8) * 72 + fo + 2 * tg));
                    fmd[mt][0] += xf0.x * acc[mt][t][0] + xf0.y * acc[mt][t][1];
                    fmd[mt][1] += xf1.x * acc[mt][t][2] + xf1.y * acc[mt][t][3];
                }
            }
        }
    }
    if (nq == 3) {   // FM output
        #pragma unroll
        for (int mt = 0; mt < 2; mt++) {
            #pragma unroll
            for (int i = 0; i < 2; i++) {
                fmd[mt][i] += __shfl_xor_sync(0xffffffffu, fmd[mt][i], 1);
                fmd[mt][i] += __shfl_xor_sync(0xffffffffu, fmd[mt][i], 2);
            }
        }
        if (tg == 0) {
            float C0 = __ldg(&g_c0[0]);
            #pragma unroll
            for (int mt = 0; mt < 2; mt++) {
                int r0 = rbase + mt * 16 + g;
                out[(size_t)(b0 + r0) * 129]     = C0 + fmd[mt][0];
                out[(size_t)(b0 + r0 + 8) * 129] = C0 + fmd[mt][1];
            }
        }
    }

    // ---- GEMM2: out[:,1:] = relu(h1 @ W2T + b2), 8 double-buffered chunks ----
    float acc2[2][4][4];
    #pragma unroll
    for (int t = 0; t < 4; t++) {
        int k0 = nq * 32 + t * 8;
        float2 bb = __ldg((const float2*)(b2 + k0 + 2 * tg));
        acc2[0][t][0] = bb.x; acc2[0][t][1] = bb.y; acc2[0][t][2] = bb.x; acc2[0][t][3] = bb.y;
        acc2[1][t][0] = bb.x; acc2[1][t][1] = bb.y; acc2[1][t][2] = bb.x; acc2[1][t][3] = bb.y;
    }
    #pragma unroll 1
    for (int c = 0; c < 8; c++) {
        asm volatile("cp.async.wait_group 0;" ::: "memory");
        __syncthreads();                       // c=0 also gates h1 readiness
        if (c < 7) {
            unsigned* nb = ((c + 1) & 1) ? wfB : wfA;
            unsigned dstw = (unsigned)__cvta_generic_to_shared(nb) + tid * 16;
            const char* srcw = (const char*)g_W2pack + (c + 1) * 8192 + tid * 16;
            cp_async16(dstw, srcw);
            cp_async16(dstw + 4096, srcw + 4096);
            cp_commit();
        }
        const unsigned* wfb = (c & 1) ? wfB : wfA;
        #pragma unroll
        for (int itl = 0; itl < 2; itl++) {
            int it = c * 2 + itl;
            unsigned aa0[4], aa1[4];
            ldsm_x4(aa0[0], aa0[1], aa0[2], aa0[3], h1_lm0 + it * 32);
            ldsm_x4(aa1[0], aa1[1], aa1[2], aa1[3], h1_lm1 + it * 32);
            const uint2* bp = (const uint2*)wfb + (itl * 16 + nq * 4) * 32 + l;
            #pragma unroll
            for (int t = 0; t < 4; t++) {
                uint2 bb = bp[t * 32];
                mma_fp16(acc2[0][t], aa0[0], aa0[1], aa0[2], aa0[3], bb.x, bb.y);
                mma_fp16(acc2[1][t], aa1[0], aa1[1], aa1[2], aa1[3], bb.x, bb.y);
            }
        }
    }
    #pragma unroll
    for (int mt = 0; mt < 2; mt++) {
        #pragma unroll
        for (int t = 0; t < 4; t++) {
            int k0 = nq * 32 + t * 8 + 2 * tg;
            int r0 = rbase + mt * 16 + g;
            size_t o0 = (size_t)(b0 + r0) * 129 + 1 + k0;
            size_t o1 = (size_t)(b0 + r0 + 8) * 129 + 1 + k0;
            out[o0]     = fmaxf(acc2[mt][t][0], 0.f);
            out[o0 + 1] = fmaxf(acc2[mt][t][1], 0.f);
            out[o1]     = fmaxf(acc2[mt][t][2], 0.f);
            out[o1 + 1] = fmaxf(acc2[mt][t][3], 0.f);
        }
    }
}

// ---------------- launch ----------------
extern "C" void kernel_launch(void* const* d_in, const int* in_sizes, int n_in,
                              void* d_out, int out_size) {
    const float* x   = (const float*)d_in[0];
    const float* emb = (const float*)d_in[1];
    const float* Wc  = (const float*)d_in[2];
    const float* bc  = (const float*)d_in[3];
    const float* Wf  = (const float*)d_in[4];
    const float* bf  = (const float*)d_in[5];
    const float* W1  = (const float*)d_in[6];
    const float* b1  = (const float*)d_in[7];
    const float* W2  = (const float*)d_in[8];
    const float* b2  = (const float*)d_in[9];
    float* out = (float*)d_out;

    prep_all<<<48, 256>>>(emb, Wc, bc, Wf, bf, W1, b1, W2);
    cudaFuncSetAttribute(deepfm_main, cudaFuncAttributeMaxDynamicSharedMemorySize, SMEM_BYTES);
    deepfm_main<<<1024, 256, SMEM_BYTES>>>(x, b2, out);
}

// round 6
// speedup vs baseline: 5.6936x; 1.1858x over previous
#include <cuda_runtime.h>
#include <cuda_fp16.h>

// ---------------- smem layout (u32 units) ----------------
#define OFF_H1  2304                 // xs: 64x72 halves = 2304 u32
#define SMEM_U32 10752               // h1: 64x264 halves = 8448 u32
#define SMEM_BYTES (SMEM_U32 * 4)    // 43008

// device scratch
__device__ unsigned g_A1pack[10240];   // GEMM1 B frags (fp16x2): [A1 | Q], 320 cols
__device__ unsigned g_W2pack[16384];   // GEMM2 B frags (fp16x2)
__device__ float    g_c1[256];
__device__ float    g_c0[1];

__device__ __forceinline__ unsigned pack_h2(float a, float b) {
    __half2 h = __floats2half2_rn(a, b);
    return *(unsigned*)&h;
}
__device__ __forceinline__ void mma_fp16(float* c, unsigned a0, unsigned a1,
                                         unsigned a2, unsigned a3,
                                         unsigned b0, unsigned b1) {
    asm volatile("mma.sync.aligned.m16n8k16.row.col.f32.f16.f16.f32 "
                 "{%0,%1,%2,%3}, {%4,%5,%6,%7}, {%8,%9}, {%0,%1,%2,%3};"
                 : "+f"(c[0]), "+f"(c[1]), "+f"(c[2]), "+f"(c[3])
                 : "r"(a0), "r"(a1), "r"(a2), "r"(a3), "r"(b0), "r"(b1));
}
__device__ __forceinline__ void ldsm_x4(unsigned& r0, unsigned& r1, unsigned& r2,
                                        unsigned& r3, unsigned saddr) {
    asm volatile("ldmatrix.sync.aligned.m8n8.x4.shared.b16 {%0,%1,%2,%3}, [%4];"
                 : "=r"(r0), "=r"(r1), "=r"(r2), "=r"(r3) : "r"(saddr));
}

// =============== merged prep kernel: 48 blocks (unchanged from R5) ===============
__global__ void prep_all(const float* __restrict__ emb, const float* __restrict__ Wc,
                         const float* __restrict__ bc,  const float* __restrict__ Wf,
                         const float* __restrict__ bf,  const float* __restrict__ W1,
                         const float* __restrict__ b1,  const float* __restrict__ W2) {
    __shared__ __align__(16) float shm[4160];
    int b = blockIdx.x, tid = threadIdx.x;

    if (b < 32) {
        float* dv   = shm;
        float* base = shm + 1024;
        float* WcA  = shm + 2048;
        float* WcB  = shm + 2080;
        for (int e = tid; e < 1024; e += 256) {
            int f = e >> 4, d = e & 15;
            if (f < 62) { dv[e] = emb[f * 32 + 16 + d] - emb[f * 32 + d]; base[e] = emb[f * 32 + d]; }
            else        { dv[e] = 0.f; base[e] = bc[e - 992]; }
        }
        if (tid < 32) { WcA[tid] = Wc[tid * 2]; WcB[tid] = Wc[tid * 2 + 1]; }
        __syncthreads();

        int w = tid >> 5, l = tid & 31;
        int j = b * 8 + w;
        const float4* wrow = (const float4*)(W1 + j * 1024);
        float cp = 0.f;
        #pragma unroll
        for (int r = 0; r < 8; r++) {
            int q = l + 32 * r;
            float4 wv = __ldg(wrow + q);
            int e0 = q * 4;
            float4 dvv = *(const float4*)(dv + e0);
            float4 bsv = *(const float4*)(base + e0);
            float pd = wv.x * dvv.x + wv.y * dvv.y + wv.z * dvv.z + wv.w * dvv.w;
            cp += wv.x * bsv.x + wv.y * bsv.y + wv.z * bsv.z + wv.w * bsv.w;
            pd += __shfl_xor_sync(0xffffffffu, pd, 1);
            pd += __shfl_xor_sync(0xffffffffu, pd, 2);
            float s62 = 0.f, s63 = 0.f;
            if (r == 7) {
                float p0 = 0.f, p1 = 0.f;
                if (l >= 24) {
                    int m0 = e0 - 992;
                    float4 wa = *(const float4*)(WcA + m0);
                    float4 wb = *(const float4*)(WcB + m0);
                    p0 = wv.x * wa.x + wv.y * wa.y + wv.z * wa.z + wv.w * wa.w;
                    p1 = wv.x * wb.x + wv.y * wb.y + wv.z * wb.z + wv.w * wb.w;
                }
                p0 += __shfl_xor_sync(0xffffffffu, p0, 1);
                p0 += __shfl_xor_sync(0xffffffffu, p0, 2);
                p0 += __shfl_xor_sync(0xffffffffu, p0, 4);
                p1 += __shfl_xor_sync(0xffffffffu, p1, 1);
                p1 += __shfl_xor_sync(0xffffffffu, p1, 2);
                p1 += __shfl_xor_sync(0xffffffffu, p1, 4);
                s62 = p0; s63 = p1;
            }
            float vnext = __shfl_sync(0xffffffffu, pd, (l + 4) & 31);
            int gidx = l >> 2;
            if ((l & 7) == 0) {
                float e0v = pd, e1v = vnext;
                if (r == 7 && gidx == 6) { e0v = s62; e1v = s63; }
                int p = (gidx >> 1) + 4 * r;
                int kt = p >> 3, reg = (p >> 2) & 1, tgx = p & 3;
                g_A1pack[((kt * 40 + (j >> 3)) * 32 + (j & 7) * 4 + tgx) * 2 + reg] =
                    pack_h2(e0v, e1v);
            }
        }
        #pragma unroll
        for (int o = 16; o; o >>= 1) cp += __shfl_xor_sync(0xffffffffu, cp, o);
        if (l == 0) g_c1[j] = cp + b1[j];

    } else if (b < 40) {
        int c = b - 32;
        float* w2s = shm;
        for (int q = tid; q < 1024; q += 256) {
            int row = q >> 3, f4 = q & 7;
            *(float4*)(w2s + row * 32 + f4 * 4) =
                __ldg((const float4*)(W2 + row * 256 + c * 32 + f4 * 4));
        }
        __syncthreads();
        for (int e = tid; e < 2048; e += 256) {
            int reg = e & 1, l2 = (e >> 1) & 31, nt = (e >> 6) & 15, itl = e >> 10;
            int gg = l2 >> 2, tgx = l2 & 3;
            int il = itl * 16 + reg * 8 + 2 * tgx;
            int k  = nt * 8 + gg;
            g_W2pack[c * 2048 + e] = pack_h2(w2s[k * 32 + il], w2s[k * 32 + il + 1]);
        }

    } else {
        int qb = b - 40;
        float (*v)[16] = (float(*)[16])shm;
        float* u  = shm + 1024;
        float* tS = shm + 1040;
        float* sS = shm + 1104;
        float* Rs = shm + 1168;
        for (int idx = tid; idx < 1024; idx += 256) {
            int f = idx >> 4, d = idx & 15;
            float val;
            if (f < 62)       val = emb[f * 32 + 16 + d] - emb[f * 32 + d];
            else if (f == 62) val = Wc[d * 2]     + Wc[(16 + d) * 2];
            else              val = Wc[d * 2 + 1] + Wc[(16 + d) * 2 + 1];
            v[f][d] = val;
        }
        if (tid < 16) {
            float s = bc[tid] + bc[16 + tid];
            for (int f = 0; f < 62; f++) s += emb[f * 32 + tid];
            u[tid] = s;
        }
        if (tid == 0) {
            float r = 0.f;
            for (int m = 0; m < 32; m++) r += Wc[m * 2] * Wc[m * 2 + 1];
            Rs[0] = r;
        }
        __syncthreads();
        if (tid < 64) {
            float t = 0.f, s = 0.f;
            if (tid < 62) {
                #pragma unroll
                for (int d = 0; d < 16; d++) { t += emb[tid * 32 + d] * v[tid][d]; s += v[tid][d] * v[tid][d]; }
            } else {
                int jc = tid - 62;
                for (int m = 0; m < 32; m++) { float wv = Wc[m * 2 + jc]; t += bc[m] * wv; s += wv * wv; }
            }
            tS[tid] = t; sS[tid] = s;
        }
        __syncthreads();
        int e = qb * 256 + tid;
        int gc = e >> 5, p = e & 31, f0 = 2 * p;
        float q2[2];
        #pragma unroll
        for (int h = 0; h < 2; h++) {
            int fr = f0 + h;
            if (fr == gc) {
                float uv = 0.f, vv = 0.f;
                #pragma unroll
                for (int d = 0; d < 16; d++) { uv += u[d] * v[fr][d]; vv += v[fr][d] * v[fr][d]; }
                q2[h] = uv - tS[fr] + 0.5f * (vv - sS[fr]) + Wf[fr];
            } else {
                float dp = 0.f;
                #pragma unroll
                for (int d = 0; d < 16; d++) dp += v[fr][d] * v[gc][d];
                float rr = ((fr == 62 && gc == 63) || (fr == 63 && gc == 62)) ? Rs[0] : 0.f;
                q2[h] = 0.5f * (dp - rr);
            }
        }
        int kt = p >> 3, reg = (p >> 2) & 1, tgx = p & 3;
        g_A1pack[((kt * 40 + 32 + (gc >> 3)) * 32 + (gc & 7) * 4 + tgx) * 2 + reg] =
            pack_h2(q2[0], q2[1]);
        if (qb == 0 && tid == 0) {
            float uu = 0.f;
            for (int d = 0; d < 16; d++) uu += u[d] * u[d];
            float e2 = 0.f;
            for (int f = 0; f < 62; f++)
                for (int d = 0; d < 16; d++) { float ev = emb[f * 32 + d]; e2 += ev * ev; }
            for (int m = 0; m < 32; m++) e2 += bc[m] * bc[m];
            g_c0[0] = bf[0] + 0.5f * (uu - e2);
        }
    }
}

// =============== fused main kernel: B-frags straight from L2 ===============
__global__ __launch_bounds__(256, 3) void deepfm_main(
    const float* __restrict__ x, const float* __restrict__ b2, float* __restrict__ out) {
    extern __shared__ unsigned smu[];
    __half* xs = (__half*)smu;              // [64][72]
    __half* h1 = (__half*)(smu + OFF_H1);   // [64][264]

    const int tid = threadIdx.x;
    const int b0  = blockIdx.x * 64;

    // ---- stage x (fp32 -> fp16) ----
    {
        int s = tid >> 2, q = tid & 3;
        const float4* xr = (const float4*)(x + (size_t)(b0 + s) * 64 + q * 16);
        float4 v0 = __ldg(xr), v1 = __ldg(xr + 1), v2 = __ldg(xr + 2), v3 = __ldg(xr + 3);
        __half2* dst = (__half2*)(xs + s * 72 + q * 16);
        dst[0] = __floats2half2_rn(v0.x, v0.y); dst[1] = __floats2half2_rn(v0.z, v0.w);
        dst[2] = __floats2half2_rn(v1.x, v1.y); dst[3] = __floats2half2_rn(v1.z, v1.w);
        dst[4] = __floats2half2_rn(v2.x, v2.y); dst[5] = __floats2half2_rn(v2.z, v2.w);
        dst[6] = __floats2half2_rn(v3.x, v3.y); dst[7] = __floats2half2_rn(v3.z, v3.w);
    }
    __syncthreads();

    const int w = tid >> 5, l = tid & 31, g = l >> 2, tg = l & 3;
    const int mh = w & 1, nq = w >> 1;           // 2 m-halves x 4 n-quarters
    const int lrow = l & 15, lcol = l >> 4;
    const int rbase = mh * 32;

    unsigned xs_lm0 = (unsigned)__cvta_generic_to_shared(xs + (rbase + lrow) * 72 + lcol * 8);
    unsigned xs_lm1 = xs_lm0 + 16 * 72 * 2;
    unsigned h1_lm0 = (unsigned)__cvta_generic_to_shared(h1 + (rbase + lrow) * 264 + lcol * 8);
    unsigned h1_lm1 = h1_lm0 + 16 * 264 * 2;

    // ---- GEMM1: z[64 x 320] = x @ [A1 | Q], B-frags from L2 with prefetch ----
    float fmd[2][2] = {{0.f, 0.f}, {0.f, 0.f}};
    const int ntb = nq * 10;
    #pragma unroll 1
    for (int pass = 0; pass < 2; pass++) {
        int nt0 = ntb + pass * 5;
        const uint2* bbase = (const uint2*)g_A1pack + nt0 * 32 + l;
        uint2 bc_[5];
        #pragma unroll
        for (int t = 0; t < 5; t++) bc_[t] = __ldg(bbase + t * 32);

        float acc[2][5][4];
        #pragma unroll
        for (int t = 0; t < 5; t++) {
            int j0 = (nt0 + t) * 8;
            float c0v = 0.f, c1v = 0.f;
            if (j0 < 256) { float2 cc = __ldg((const float2*)(g_c1 + j0 + 2 * tg)); c0v = cc.x; c1v = cc.y; }
            acc[0][t][0] = c0v; acc[0][t][1] = c1v; acc[0][t][2] = c0v; acc[0][t][3] = c1v;
            acc[1][t][0] = c0v; acc[1][t][1] = c1v; acc[1][t][2] = c0v; acc[1][t][3] = c1v;
        }
        #pragma unroll
        for (int kt = 0; kt < 4; kt++) {
            uint2 bn_[5];
            if (kt < 3) {
                const uint2* bp = bbase + (kt + 1) * 40 * 32;
                #pragma unroll
                for (int t = 0; t < 5; t++) bn_[t] = __ldg(bp + t * 32);
            }
            unsigned am0[4], am1[4];
            ldsm_x4(am0[0], am0[1], am0[2], am0[3], xs_lm0 + kt * 32);
            ldsm_x4(am1[0], am1[1], am1[2], am1[3], xs_lm1 + kt * 32);
            #pragma unroll
            for (int t = 0; t < 5; t++) {
                mma_fp16(acc[0][t], am0[0], am0[1], am0[2], am0[3], bc_[t].x, bc_[t].y);
                mma_fp16(acc[1][t], am1[0], am1[1], am1[2], am1[3], bc_[t].x, bc_[t].y);
            }
            if (kt < 3) {
                #pragma unroll
                for (int t = 0; t < 5; t++) bc_[t] = bn_[t];
            }
        }
        #pragma unroll
        for (int t = 0; t < 5; t++) {
            int j0 = (nt0 + t) * 8;
            #pragma unroll
            for (int mt = 0; mt < 2; mt++) {
                int r0 = rbase + mt * 16 + g;
                if (j0 < 256) {
                    *(__half2*)(h1 + r0 * 264 + j0 + 2 * tg) =
                        __floats2half2_rn(fmaxf(acc[mt][t][0], 0.f), fmaxf(acc[mt][t][1], 0.f));
                    *(__half2*)(h1 + (r0 + 8) * 264 + j0 + 2 * tg) =
                        __floats2half2_rn(fmaxf(acc[mt][t][2], 0.f), fmaxf(acc[mt][t][3], 0.f));
                } else {
                    int fo = j0 - 256;
                    float2 xf0 = __half22float2(*(__half2*)(xs + r0 * 72 + fo + 2 * tg));
                    float2 xf1 = __half22float2(*(__half2*)(xs + (r0 + 8) * 72 + fo + 2 * tg));
                    fmd[mt][0] += xf0.x * acc[mt][t][0] + xf0.y * acc[mt][t][1];
                    fmd[mt][1] += xf1.x * acc[mt][t][2] + xf1.y * acc[mt][t][3];
                }
            }
        }
    }
    if (nq == 3) {   // FM output
        #pragma unroll
        for (int mt = 0; mt < 2; mt++) {
            #pragma unroll
            for (int i = 0; i < 2; i++) {
                fmd[mt][i] += __shfl_xor_sync(0xffffffffu, fmd[mt][i], 1);
                fmd[mt][i] += __shfl_xor_sync(0xffffffffu, fmd[mt][i], 2);
            }
        }
        if (tg == 0) {
            float C0 = __ldg(&g_c0[0]);
            #pragma unroll
            for (int mt = 0; mt < 2; mt++) {
                int r0 = rbase + mt * 16 + g;
                out[(size_t)(b0 + r0) * 129]     = C0 + fmd[mt][0];
                out[(size_t)(b0 + r0 + 8) * 129] = C0 + fmd[mt][1];
            }
        }
    }
    __syncthreads();   // h1 complete

    // ---- GEMM2: out[:,1:] = relu(h1 @ W2T + b2), B-frags from L2 with prefetch ----
    float acc2[2][4][4];
    #pragma unroll
    for (int t = 0; t < 4; t++) {
        int k0 = nq * 32 + t * 8;
        float2 bb = __ldg((const float2*)(b2 + k0 + 2 * tg));
        acc2[0][t][0] = bb.x; acc2[0][t][1] = bb.y; acc2[0][t][2] = bb.x; acc2[0][t][3] = bb.y;
        acc2[1][t][0] = bb.x; acc2[1][t][1] = bb.y; acc2[1][t][2] = bb.x; acc2[1][t][3] = bb.y;
    }
    {
        const uint2* wbase = (const uint2*)g_W2pack + nq * 4 * 32 + l;
        uint2 wc_[4];
        #pragma unroll
        for (int t = 0; t < 4; t++) wc_[t] = __ldg(wbase + t * 32);
        #pragma unroll
        for (int it = 0; it < 16; it++) {
            uint2 wn_[4];
            if (it < 15) {
                const uint2* wp = wbase + (it + 1) * 16 * 32;
                #pragma unroll
                for (int t = 0; t < 4; t++) wn_[t] = __ldg(wp + t * 32);
            }
            unsigned aa0[4], aa1[4];
            ldsm_x4(aa0[0], aa0[1], aa0[2], aa0[3], h1_lm0 + it * 32);
            ldsm_x4(aa1[0], aa1[1], aa1[2], aa1[3], h1_lm1 + it * 32);
            #pragma unroll
            for (int t = 0; t < 4; t++) {
                mma_fp16(acc2[0][t], aa0[0], aa0[1], aa0[2], aa0[3], wc_[t].x, wc_[t].y);
                mma_fp16(acc2[1][t], aa1[0], aa1[1], aa1[2], aa1[3], wc_[t].x, wc_[t].y);
            }
            if (it < 15) {
                #pragma unroll
                for (int t = 0; t < 4; t++) wc_[t] = wn_[t];
            }
        }
    }
    #pragma unroll
    for (int mt = 0; mt < 2; mt++) {
        #pragma unroll
        for (int t = 0; t < 4; t++) {
            int k0 = nq * 32 + t * 8 + 2 * tg;
            int r0 = rbase + mt * 16 + g;
            size_t o0 = (size_t)(b0 + r0) * 129 + 1 + k0;
            size_t o1 = (size_t)(b0 + r0 + 8) * 129 + 1 + k0;
            out[o0]     = fmaxf(acc2[mt][t][0], 0.f);
            out[o0 + 1] = fmaxf(acc2[mt][t][1], 0.f);
            out[o1]     = fmaxf(acc2[mt][t][2], 0.f);
            out[o1 + 1] = fmaxf(acc2[mt][t][3], 0.f);
        }
    }
}

// ---------------- launch ----------------
extern "C" void kernel_launch(void* const* d_in, const int* in_sizes, int n_in,
                              void* d_out, int out_size) {
    const float* x   = (const float*)d_in[0];
    const float* emb = (const float*)d_in[1];
    const float* Wc  = (const float*)d_in[2];
    const float* bc  = (const float*)d_in[3];
    const float* Wf  = (const float*)d_in[4];
    const float* bf  = (const float*)d_in[5];
    const float* W1  = (const float*)d_in[6];
    const float* b1  = (const float*)d_in[7];
    const float* W2  = (const float*)d_in[8];
    const float* b2  = (const float*)d_in[9];
    float* out = (float*)d_out;

    prep_all<<<48, 256>>>(emb, Wc, bc, Wf, bf, W1, b1, W2);
    cudaFuncSetAttribute(deepfm_main, cudaFuncAttributeMaxDynamicSharedMemorySize, SMEM_BYTES);
    deepfm_main<<<1024, 256, SMEM_BYTES>>>(x, b2, out);
}